// round 1
// baseline (speedup 1.0000x reference)
#include <cuda_runtime.h>

// FocusModules: stage1 window pruning + stage3 adjacent merge.
// x: [N, 256] f32.  out (float32): [ mask1 (N) | compressed (N*256) ].
//
// One CTA per 32-token window. 1024 threads = 32 warps, warp i owns token i.
// mean_sim[i] = dot(xn_i, sum_j xn_j) / 32   (avoids the 32x32 sim matrix).

#define DIMV 64          // float4 per token (256 floats)
#define WTOK 32          // window size

__device__ __forceinline__ float warp_sum(float v) {
    #pragma unroll
    for (int o = 16; o; o >>= 1) v += __shfl_xor_sync(0xFFFFFFFFu, v, o);
    return v;
}

__device__ __forceinline__ float dot4(float4 a, float4 b) {
    return a.x * b.x + a.y * b.y + a.z * b.z + a.w * b.w;
}

__global__ void __launch_bounds__(1024, 1)
focus_kernel(const float4* __restrict__ x,
             float* __restrict__ mask_out,        // N floats (0/1)
             float4* __restrict__ comp_out,       // N*64 float4
             int nwin)
{
    // 33 rows of normalized tokens: rows 0..31 = window, row 32 = prev window's last token
    __shared__ float4 xn_s[33][DIMV];    // 33 * 256 * 4 = 33,792 B
    __shared__ float  s_s[256];          // column sums of normalized window tokens
    __shared__ float  ms_s[WTOK];        // per-token mean similarity

    const int w    = blockIdx.x;
    const int warp = threadIdx.x >> 5;
    const int lane = threadIdx.x & 31;
    const int t0   = w * WTOK;           // first global token of this window
    const int gi   = t0 + warp;          // this warp's global token

    // ---- Phase A: load token, normalize, stage into smem ----
    const float4 v0 = x[gi * DIMV + lane];
    const float4 v1 = x[gi * DIMV + 32 + lane];
    float ss = warp_sum(dot4(v0, v0) + dot4(v1, v1));
    float inv = 1.0f / fmaxf(sqrtf(ss), 1e-12f);
    const float4 n0 = make_float4(v0.x * inv, v0.y * inv, v0.z * inv, v0.w * inv);
    const float4 n1 = make_float4(v1.x * inv, v1.y * inv, v1.z * inv, v1.w * inv);
    xn_s[warp][lane]      = n0;
    xn_s[warp][32 + lane] = n1;

    // warp 0 additionally stages the previous window's last token (for the adjacent dot)
    if (warp == 0 && w > 0) {
        const int gp = t0 - 1;
        float4 p0 = x[gp * DIMV + lane];
        float4 p1 = x[gp * DIMV + 32 + lane];
        float ps = warp_sum(dot4(p0, p0) + dot4(p1, p1));
        float pinv = 1.0f / fmaxf(sqrtf(ps), 1e-12f);
        xn_s[32][lane]      = make_float4(p0.x * pinv, p0.y * pinv, p0.z * pinv, p0.w * pinv);
        xn_s[32][32 + lane] = make_float4(p1.x * pinv, p1.y * pinv, p1.z * pinv, p1.w * pinv);
    }
    __syncthreads();

    // ---- Phase B: column sums of the 32 normalized window tokens ----
    if (threadIdx.x < 256) {
        const float* base = (const float*)xn_s;  // row stride = 256 floats
        const int c = threadIdx.x;
        float acc = 0.0f;
        #pragma unroll
        for (int r = 0; r < WTOK; r++) acc += base[r * 256 + c];
        s_s[c] = acc;
    }
    __syncthreads();

    // ---- Phase C: per-token dots + stage-3 mask + compressed write ----
    const float4* sv = (const float4*)s_s;
    const float4 s0 = sv[lane];
    const float4 s1 = sv[32 + lane];
    const int prow = (warp == 0) ? 32 : (warp - 1);
    const float4 p0 = xn_s[prow][lane];
    const float4 p1 = xn_s[prow][32 + lane];

    float dms  = dot4(n0, s0) + dot4(n1, s1);
    float dadj = dot4(n0, p0) + dot4(n1, p1);
    #pragma unroll
    for (int o = 16; o; o >>= 1) {
        dms  += __shfl_xor_sync(0xFFFFFFFFu, dms,  o);
        dadj += __shfl_xor_sync(0xFFFFFFFFu, dadj, o);
    }
    if (lane == 0) ms_s[warp] = dms * (1.0f / 32.0f);

    const bool mask3 = (gi == 0) || (dadj < 0.7f);
    const float4 z = make_float4(0.f, 0.f, 0.f, 0.f);
    comp_out[gi * DIMV + lane]      = mask3 ? v0 : z;
    comp_out[gi * DIMV + 32 + lane] = mask3 ? v1 : z;
    __syncthreads();

    // ---- Phase D: window statistics + stage-1 mask (warp 0 only) ----
    if (warp == 0) {
        const float m = ms_s[lane];
        float mu = warp_sum(m) * (1.0f / 32.0f);
        float d = m - mu;
        float var = warp_sum(d * d) * (1.0f / 31.0f);   // ddof=1
        float sd = sqrtf(var);
        bool keep = !(m > mu + sd);
        unsigned bal = __ballot_sync(0xFFFFFFFFu, keep);
        if (bal == 0u) {
            // fallback: keep argmin(mean_sim), first index on ties
            float bv = m; int bi = lane;
            #pragma unroll
            for (int o = 16; o; o >>= 1) {
                float ov = __shfl_xor_sync(0xFFFFFFFFu, bv, o);
                int   oi = __shfl_xor_sync(0xFFFFFFFFu, bi, o);
                if (ov < bv || (ov == bv && oi < bi)) { bv = ov; bi = oi; }
            }
            keep = (lane == bi);
        }
        mask_out[t0 + lane] = keep ? 1.0f : 0.0f;
    }
}

extern "C" void kernel_launch(void* const* d_in, const int* in_sizes, int n_in,
                              void* d_out, int out_size)
{
    const float4* x = (const float4*)d_in[0];
    const int N = in_sizes[0] / 256;       // tokens
    const int nwin = N / WTOK;             // windows

    float* out = (float*)d_out;
    float*  mask_out = out;                // first N floats
    float4* comp_out = (float4*)(out + N); // N is a multiple of 4 -> 16B aligned

    focus_kernel<<<nwin, 1024>>>(x, mask_out, comp_out, nwin);
}

// round 3
// speedup vs baseline: 1.7241x; 1.7241x over previous
#include <cuda_runtime.h>

// FocusModules: stage1 window pruning + stage3 adjacent merge.
// x: [N, 256] f32.  out (float32): [ mask1 (N) | compressed (N*256) ].
//
// One CTA (512 thr, 16 warps) per 32-token window; each warp owns 2 tokens.
// mean_sim[i] = dot(xn_i, sum_j xn_j)/32 = inv_i * dot(raw_i, s)/32,
// where s[c] = sum_r raw[r][c]*inv_r  (avoids the 32x32 sim matrix).

#define DIMV 64          // float4 per token (256 floats)
#define WTOK 32          // window size

__device__ __forceinline__ float warp_sum(float v) {
    #pragma unroll
    for (int o = 16; o; o >>= 1) v += __shfl_xor_sync(0xFFFFFFFFu, v, o);
    return v;
}

__device__ __forceinline__ float dot4(float4 a, float4 b) {
    return a.x * b.x + a.y * b.y + a.z * b.z + a.w * b.w;
}

__global__ void __launch_bounds__(512, 3)
focus_kernel(const float4* __restrict__ x,
             float* __restrict__ mask_out,        // N floats (0/1)
             float4* __restrict__ comp_out)       // N*64 float4
{
    // Raw token rows: 0..31 = window tokens, 32 = previous window's last token.
    __shared__ float4 xs[33][DIMV];                  // 33 KB, 16B aligned
    __shared__ __align__(16) float s_s[256];         // weighted column sums (read as float4)
    __shared__ float  inv_s[33];                     // per-row 1/||x||
    __shared__ float  ms_s[WTOK];                    // per-token mean similarity

    const int w    = blockIdx.x;
    const int warp = threadIdx.x >> 5;
    const int lane = threadIdx.x & 31;
    const int t0   = w * WTOK;
    const int tA   = 2 * warp;           // local token ids for this warp
    const int tB   = 2 * warp + 1;

    // ---- Phase A: load 2 tokens, compute norms, stage raw into smem ----
    const float4* xa = x + (size_t)(t0 + tA) * DIMV;
    const float4* xb = x + (size_t)(t0 + tB) * DIMV;
    const float4 a0 = xa[lane], a1 = xa[32 + lane];
    const float4 b0 = xb[lane], b1 = xb[32 + lane];

    float sa = dot4(a0, a0) + dot4(a1, a1);
    float sb = dot4(b0, b0) + dot4(b1, b1);
    #pragma unroll
    for (int o = 16; o; o >>= 1) {
        sa += __shfl_xor_sync(0xFFFFFFFFu, sa, o);
        sb += __shfl_xor_sync(0xFFFFFFFFu, sb, o);
    }
    const float invA = 1.0f / fmaxf(sqrtf(sa), 1e-12f);
    const float invB = 1.0f / fmaxf(sqrtf(sb), 1e-12f);

    xs[tA][lane] = a0;  xs[tA][32 + lane] = a1;
    xs[tB][lane] = b0;  xs[tB][32 + lane] = b1;
    if (lane == 0) { inv_s[tA] = invA; inv_s[tB] = invB; }

    // warp 0 stages the previous window's last token into row 32
    if (warp == 0 && w > 0) {
        const float4* xp = x + (size_t)(t0 - 1) * DIMV;
        float4 p0 = xp[lane], p1 = xp[32 + lane];
        float sp = warp_sum(dot4(p0, p0) + dot4(p1, p1));
        xs[32][lane] = p0;  xs[32][32 + lane] = p1;
        if (lane == 0) inv_s[32] = 1.0f / fmaxf(sqrtf(sp), 1e-12f);
    }
    __syncthreads();

    // ---- Phase B: weighted column sums (normalized-token column sums) ----
    if (threadIdx.x < 256) {
        const float* base = (const float*)xs;   // row stride = 256 floats
        const int c = threadIdx.x;
        float acc = 0.0f;
        #pragma unroll
        for (int r = 0; r < WTOK; r++) acc += base[r * 256 + c] * inv_s[r];
        s_s[c] = acc;
    }
    __syncthreads();

    // ---- Phase C: per-token dots + stage-3 mask + compressed write ----
    const float4* sv = (const float4*)s_s;
    const float4 s0 = sv[lane];
    const float4 s1 = sv[32 + lane];

    // token A: adjacent partner is smem row (tA-1) or row 32 (prev window)
    {
        const int prow = (tA == 0) ? 32 : (tA - 1);
        const float4 p0 = xs[prow][lane];
        const float4 p1 = xs[prow][32 + lane];
        float dms  = dot4(a0, s0) + dot4(a1, s1);
        float dadj = dot4(a0, p0) + dot4(a1, p1);
        #pragma unroll
        for (int o = 16; o; o >>= 1) {
            dms  += __shfl_xor_sync(0xFFFFFFFFu, dms,  o);
            dadj += __shfl_xor_sync(0xFFFFFFFFu, dadj, o);
        }
        if (lane == 0) ms_s[tA] = invA * dms * (1.0f / 32.0f);
        const bool m3 = (t0 + tA == 0) || (invA * inv_s[prow] * dadj < 0.7f);
        const float4 z = make_float4(0.f, 0.f, 0.f, 0.f);
        float4* dst = comp_out + (size_t)(t0 + tA) * DIMV;
        dst[lane]      = m3 ? a0 : z;
        dst[32 + lane] = m3 ? a1 : z;
    }
    // token B: adjacent partner is token A (in registers)
    {
        float dms  = dot4(b0, s0) + dot4(b1, s1);
        float dadj = dot4(b0, a0) + dot4(b1, a1);
        #pragma unroll
        for (int o = 16; o; o >>= 1) {
            dms  += __shfl_xor_sync(0xFFFFFFFFu, dms,  o);
            dadj += __shfl_xor_sync(0xFFFFFFFFu, dadj, o);
        }
        if (lane == 0) ms_s[tB] = invB * dms * (1.0f / 32.0f);
        const bool m3 = (invB * invA * dadj < 0.7f);
        const float4 z = make_float4(0.f, 0.f, 0.f, 0.f);
        float4* dst = comp_out + (size_t)(t0 + tB) * DIMV;
        dst[lane]      = m3 ? b0 : z;
        dst[32 + lane] = m3 ? b1 : z;
    }
    __syncthreads();

    // ---- Phase D: window statistics + stage-1 mask (warp 0 only) ----
    if (warp == 0) {
        const float m = ms_s[lane];
        float mu = warp_sum(m) * (1.0f / 32.0f);
        float d = m - mu;
        float var = warp_sum(d * d) * (1.0f / 31.0f);   // ddof=1
        float sd = sqrtf(var);
        bool keep = !(m > mu + sd);
        unsigned bal = __ballot_sync(0xFFFFFFFFu, keep);
        if (bal == 0u) {
            // fallback: keep argmin(mean_sim), first index on ties
            float bv = m; int bi = lane;
            #pragma unroll
            for (int o = 16; o; o >>= 1) {
                float ov = __shfl_xor_sync(0xFFFFFFFFu, bv, o);
                int   oi = __shfl_xor_sync(0xFFFFFFFFu, bi, o);
                if (ov < bv || (ov == bv && oi < bi)) { bv = ov; bi = oi; }
            }
            keep = (lane == bi);
        }
        mask_out[t0 + lane] = keep ? 1.0f : 0.0f;
    }
}

extern "C" void kernel_launch(void* const* d_in, const int* in_sizes, int n_in,
                              void* d_out, int out_size)
{
    const float4* x = (const float4*)d_in[0];
    const int N = in_sizes[0] / 256;       // tokens
    const int nwin = N / WTOK;             // windows

    float* out = (float*)d_out;
    float*  mask_out = out;                // first N floats
    float4* comp_out = (float4*)(out + N); // N multiple of 4 -> 16B aligned

    focus_kernel<<<nwin, 512>>>(x, mask_out, comp_out);
}